// round 6
// baseline (speedup 1.0000x reference)
#include <cuda_runtime.h>
#include <cuda_bf16.h>
#include <cstdint>

#define N_NODES 50000
#define N_EDGES 800000
#define HID 128
#define N_LAYERS 7
#define N_GRAPHS 500

// ---------------- scratch (device globals; zero-init at module load) ----------------
__device__ __nv_bfloat16 g_fh0[N_NODES * HID];   // feature ping-pong buffers (hi/lo split)
__device__ __nv_bfloat16 g_fl0[N_NODES * HID];
__device__ __nv_bfloat16 g_fh1[N_NODES * HID];
__device__ __nv_bfloat16 g_fl1[N_NODES * HID];
__device__ __nv_bfloat16 g_wt[N_LAYERS * 65536]; // [layer][hi nxk | lo nxk], n=128, k=256
__device__ float g_pooled[N_GRAPHS * HID];       // zeroed by k_final each replay
__device__ float g_invdeg[N_NODES];
__device__ int   g_deg[N_NODES];                 // zeroed by k_pool each replay
__device__ int   g_rowptr[N_NODES + 1];
__device__ int   g_cursor[N_NODES];              // zeroed by k_pool each replay
__device__ int   g_col[N_EDGES];

// ---------------- helpers ----------------
__device__ __forceinline__ uint32_t smem_u32(const void* p) {
    uint32_t a;
    asm("{ .reg .u64 t; cvta.to.shared.u64 t, %1; cvt.u32.u64 %0, t; }" : "=r"(a) : "l"(p));
    return a;
}
__device__ __forceinline__ uint32_t pack_hi2(float a, float b) {
    __nv_bfloat162 t = __floats2bfloat162_rn(a, b);
    return *reinterpret_cast<uint32_t*>(&t);
}
__device__ __forceinline__ uint32_t pack_lo2(float a, float b) {
    float ra = a - __bfloat162float(__float2bfloat16_rn(a));
    float rb = b - __bfloat162float(__float2bfloat16_rn(b));
    __nv_bfloat162 t = __floats2bfloat162_rn(ra, rb);
    return *reinterpret_cast<uint32_t*>(&t);
}
__device__ __forceinline__ float2 up2(uint32_t u) {
    __nv_bfloat162 b = *reinterpret_cast<__nv_bfloat162*>(&u);
    return __bfloat1622float2(b);
}
__device__ __forceinline__ void ldsm_x4(uint32_t* r, uint32_t addr) {
    asm volatile("ldmatrix.sync.aligned.m8n8.x4.shared.b16 {%0,%1,%2,%3}, [%4];"
                 : "=r"(r[0]), "=r"(r[1]), "=r"(r[2]), "=r"(r[3]) : "r"(addr));
}
__device__ __forceinline__ void ldsm_x2(uint32_t* r, uint32_t addr) {
    asm volatile("ldmatrix.sync.aligned.m8n8.x2.shared.b16 {%0,%1}, [%2];"
                 : "=r"(r[0]), "=r"(r[1]) : "r"(addr));
}
__device__ __forceinline__ void mma_bf16(float* c, const uint32_t* a, const uint32_t* b) {
    asm volatile("mma.sync.aligned.m16n8k16.row.col.f32.bf16.bf16.f32 "
                 "{%0,%1,%2,%3}, {%4,%5,%6,%7}, {%8,%9}, {%0,%1,%2,%3};"
                 : "+f"(c[0]), "+f"(c[1]), "+f"(c[2]), "+f"(c[3])
                 : "r"(a[0]), "r"(a[1]), "r"(a[2]), "r"(a[3]), "r"(b[0]), "r"(b[1]));
}
__device__ __forceinline__ void cp16(uint32_t smaddr, const void* gaddr) {
    asm volatile("cp.async.cg.shared.global [%0], [%1], 16;" :: "r"(smaddr), "l"(gaddr));
}
__device__ __forceinline__ void cp_commit() { asm volatile("cp.async.commit_group;"); }
template <int N>
__device__ __forceinline__ void cp_wait() { asm volatile("cp.async.wait_group %0;" :: "n"(N)); }

// ---------------- launch 1: hist + weight prep + x split (independent work) ----------------
__global__ void k_pre(const int* __restrict__ dst, const float* __restrict__ x,
                      const float* __restrict__ Wl, const float* __restrict__ Wr) {
    int i = blockIdx.x * blockDim.x + threadIdx.x;
    if (i < N_EDGES) atomicAdd(&g_deg[dst[i]], 1);
    if (i < N_LAYERS * 32768) {
        int l = i >> 15;
        int r = i & 32767;
        int n = r >> 8;
        int k = r & 255;
        float w = (k < 128) ? Wl[((size_t)l * 128 + k) * 128 + n]
                            : Wr[((size_t)l * 128 + (k - 128)) * 128 + n];
        __nv_bfloat16 hb = __float2bfloat16_rn(w);
        float lf = w - __bfloat162float(hb);
        size_t bo = (size_t)l * 65536;
        g_wt[bo + (size_t)n * 256 + k] = hb;
        g_wt[bo + 32768 + (size_t)n * 256 + k] = __float2bfloat16_rn(lf);
    }
    if (i < N_NODES * HID / 4) {
        float4 v = *(const float4*)(x + (size_t)i * 4);
        uint2 h, l;
        h.x = pack_hi2(v.x, v.y); h.y = pack_hi2(v.z, v.w);
        l.x = pack_lo2(v.x, v.y); l.y = pack_lo2(v.z, v.w);
        *(uint2*)(g_fh0 + (size_t)i * 4) = h;
        *(uint2*)(g_fl0 + (size_t)i * 4) = l;
    }
}

// ---------------- launch 2: single-launch scan (redundant block prefix) ----------------
__global__ void k_scan() {
    __shared__ int s[1024];
    __shared__ int wsum[32];
    __shared__ int s_off;
    int b = blockIdx.x, t = threadIdx.x;
    // offset = sum of deg in preceding blocks
    int local = 0;
    for (int i = t; i < b * 1024; i += 1024) local += g_deg[i];
    #pragma unroll
    for (int o = 16; o; o >>= 1) local += __shfl_xor_sync(0xFFFFFFFFu, local, o);
    if ((t & 31) == 0) wsum[t >> 5] = local;
    __syncthreads();
    if (t == 0) {
        int o = 0;
        #pragma unroll
        for (int w = 0; w < 32; w++) o += wsum[w];
        s_off = o;
    }
    __syncthreads();
    int offset = s_off;
    // local inclusive scan
    int idx = b * 1024 + t;
    int v = (idx < N_NODES) ? g_deg[idx] : 0;
    s[t] = v;
    __syncthreads();
    #pragma unroll
    for (int off = 1; off < 1024; off <<= 1) {
        int u = (t >= off) ? s[t - off] : 0;
        __syncthreads();
        s[t] += u;
        __syncthreads();
    }
    if (idx < N_NODES) {
        g_rowptr[idx + 1] = offset + s[t];
        int d = v;
        g_invdeg[idx] = 1.0f / (float)(d > 0 ? d : 1);
    }
    if (b == 0 && t == 0) g_rowptr[0] = 0;
}

// ---------------- launch 3: CSR fill ----------------
__global__ void k_fill(const int* __restrict__ src, const int* __restrict__ dst) {
    int e = blockIdx.x * blockDim.x + threadIdx.x;
    if (e < N_EDGES) {
        int d = dst[e];
        int p = atomicAdd(&g_cursor[d], 1);
        g_col[g_rowptr[d] + p] = src[e];
    }
}

// ---------------- fused layer: agg (gather) + HMMA GEMM ----------------
// out rows [row0, row0+128): agg own rows into SMEM A chunks 0-3; h-half (chunks 4-7)
// + W stream via cp.async. Then 8-chunk MMA: D = Ahi*Bhi + Ahi*Blo + Alo*Bhi.
#define RS 40
#define CTB (128 * RS * 2)             // 10240 B per tile
#define OFF_AH(c) ((uint32_t)(c) * CTB)            // c in 0..7
#define OFF_AL(c) (8u * CTB + (uint32_t)(c) * CTB)
#define OFF_WH(b) (16u * CTB + (uint32_t)(b) * 2u * CTB)
#define OFF_WL(b) (OFF_WH(b) + CTB)
#define LAYER_SMEM (20 * CTB)          // 204800 B

__global__ void __launch_bounds__(256, 1) k_layer(
    const __nv_bfloat16* __restrict__ hInHi, const __nv_bfloat16* __restrict__ hInLo,
    __nv_bfloat16* __restrict__ hOutHi, __nv_bfloat16* __restrict__ hOutLo,
    const __nv_bfloat16* __restrict__ wt,   // layer base: [hi 128x256 | lo 128x256]
    const float* __restrict__ bias,
    int doRelu)
{
    extern __shared__ __align__(16) char dsm[];
    __shared__ float sBias[128];

    int t = threadIdx.x;
    int lane = t & 31;
    int wid = t >> 5;
    int warpM = wid >> 2;
    int warpN = wid & 3;
    int row0 = blockIdx.x * 128;
    uint32_t dsb = smem_u32(dsm);

    if (t < 128) sBias[t] = bias[t];

    // ---- phase 0: cp.async h-half of A (chunks 4..7) + W chunk 0 ----
    #pragma unroll
    for (int i = 0; i < 2; i++) {
        int idx = t + i * 256;               // 0..511
        int row = idx >> 2, c16 = idx & 3;
        int rg = row0 + row;
        if (rg > N_NODES - 1) rg = N_NODES - 1;
        uint32_t smoff = (uint32_t)(row * RS + c16 * 8) * 2;
        size_t ab = (size_t)rg * 256 + c16 * 16;
        #pragma unroll
        for (int c = 0; c < 4; c++) {
            cp16(dsb + OFF_AH(4 + c) + smoff, (const char*)hInHi + ab + c * 64);
            cp16(dsb + OFF_AL(4 + c) + smoff, (const char*)hInLo + ab + c * 64);
        }
        size_t wb = (size_t)row * 512 + c16 * 16;
        cp16(dsb + OFF_WH(0) + smoff, (const char*)wt + wb);
        cp16(dsb + OFF_WL(0) + smoff, (const char*)wt + 65536 + wb);
    }
    cp_commit();

    // ---- phase 1: aggregate own 128 rows -> SMEM A chunks 0..3 ----
    {
        int c = lane * 4;
        int chunk = lane >> 3;
        uint32_t aoffH = OFF_AH(chunk) + (uint32_t)((lane & 7) * 4) * 2;
        uint32_t aoffL = OFF_AL(chunk) + (uint32_t)((lane & 7) * 4) * 2;
        for (int nn = 0; nn < 16; nn++) {
            int lrow = wid * 16 + nn;
            int node = row0 + lrow;
            if (node >= N_NODES) break;
            int beg = g_rowptr[node], end = g_rowptr[node + 1];
            float a0 = 0.f, a1 = 0.f, a2 = 0.f, a3 = 0.f;
            float b0 = 0.f, b1 = 0.f, b2 = 0.f, b3 = 0.f;
            int e = beg;
            for (; e + 2 <= end; e += 2) {
                int s0 = g_col[e], s1 = g_col[e + 1];
                uint2 h0 = *(const uint2*)(hInHi + (size_t)s0 * HID + c);
                uint2 l0 = *(const uint2*)(hInLo + (size_t)s0 * HID + c);
                uint2 h1 = *(const uint2*)(hInHi + (size_t)s1 * HID + c);
                uint2 l1 = *(const uint2*)(hInLo + (size_t)s1 * HID + c);
                float2 p, q;
                p = up2(h0.x); q = up2(l0.x); a0 += p.x + q.x; a1 += p.y + q.y;
                p = up2(h0.y); q = up2(l0.y); a2 += p.x + q.x; a3 += p.y + q.y;
                p = up2(h1.x); q = up2(l1.x); b0 += p.x + q.x; b1 += p.y + q.y;
                p = up2(h1.y); q = up2(l1.y); b2 += p.x + q.x; b3 += p.y + q.y;
            }
            if (e < end) {
                int s0 = g_col[e];
                uint2 h0 = *(const uint2*)(hInHi + (size_t)s0 * HID + c);
                uint2 l0 = *(const uint2*)(hInLo + (size_t)s0 * HID + c);
                float2 p, q;
                p = up2(h0.x); q = up2(l0.x); a0 += p.x + q.x; a1 += p.y + q.y;
                p = up2(h0.y); q = up2(l0.y); a2 += p.x + q.x; a3 += p.y + q.y;
            }
            float sc = g_invdeg[node];
            a0 = (a0 + b0) * sc; a1 = (a1 + b1) * sc;
            a2 = (a2 + b2) * sc; a3 = (a3 + b3) * sc;
            uint2 hh, ll;
            hh.x = pack_hi2(a0, a1); hh.y = pack_hi2(a2, a3);
            ll.x = pack_lo2(a0, a1); ll.y = pack_lo2(a2, a3);
            uint32_t rb = (uint32_t)(lrow * RS) * 2;
            *(uint2*)(dsm + aoffH + rb) = hh;
            *(uint2*)(dsm + aoffL + rb) = ll;
        }
    }

    cp_wait<0>();
    __syncthreads();

    // ---- phase 2: 8-chunk MMA, W double-buffered ----
    float acc[4][4][4];
    #pragma unroll
    for (int i = 0; i < 4; i++)
        #pragma unroll
        for (int j = 0; j < 4; j++)
            #pragma unroll
            for (int q = 0; q < 4; q++) acc[i][j][q] = 0.0f;

    for (int c8 = 0; c8 < 8; c8++) {
        int buf = c8 & 1;
        if (c8 < 7) {
            int nb = buf ^ 1;
            #pragma unroll
            for (int i = 0; i < 2; i++) {
                int idx = t + i * 256;
                int row = idx >> 2, c16 = idx & 3;
                uint32_t smoff = (uint32_t)(row * RS + c16 * 8) * 2;
                size_t wb = (size_t)row * 512 + (size_t)(c8 + 1) * 64 + c16 * 16;
                cp16(dsb + OFF_WH(nb) + smoff, (const char*)wt + wb);
                cp16(dsb + OFF_WL(nb) + smoff, (const char*)wt + 65536 + wb);
            }
            cp_commit();
            cp_wait<1>();
        } else {
            cp_wait<0>();
        }
        __syncthreads();

        uint32_t bAh = dsb + OFF_AH(c8);
        uint32_t bAl = dsb + OFF_AL(c8);
        uint32_t bBh = dsb + OFF_WH(buf);
        uint32_t bBl = dsb + OFF_WL(buf);

        #pragma unroll
        for (int kk = 0; kk < 2; kk++) {
            uint32_t ah[4][4], al[4][4], bh[4][2], bl[4][2];
            int ar = warpM * 64 + (lane & 15);
            int akc = kk * 16 + (lane >> 4) * 8;
            #pragma unroll
            for (int mt = 0; mt < 4; mt++) {
                uint32_t off = (uint32_t)((ar + mt * 16) * RS + akc) * 2;
                ldsm_x4(ah[mt], bAh + off);
                ldsm_x4(al[mt], bAl + off);
            }
            int br = warpN * 32 + (lane & 7);
            int bkc = kk * 16 + ((lane >> 3) & 1) * 8;
            #pragma unroll
            for (int nt = 0; nt < 4; nt++) {
                uint32_t off = (uint32_t)((br + nt * 8) * RS + bkc) * 2;
                ldsm_x2(bh[nt], bBh + off);
                ldsm_x2(bl[nt], bBl + off);
            }
            #pragma unroll
            for (int mt = 0; mt < 4; mt++)
                #pragma unroll
                for (int nt = 0; nt < 4; nt++) {
                    mma_bf16(acc[mt][nt], ah[mt], bh[nt]);
                    mma_bf16(acc[mt][nt], ah[mt], bl[nt]);
                    mma_bf16(acc[mt][nt], al[mt], bh[nt]);
                }
        }
        __syncthreads();
    }

    // ---- epilogue: bias + relu + split-store hi/lo bf16 ----
    int g = lane >> 2;
    int cc = (lane & 3) * 2;
    #pragma unroll
    for (int mt = 0; mt < 4; mt++) {
        #pragma unroll
        for (int nt = 0; nt < 4; nt++) {
            int col = warpN * 32 + nt * 8 + cc;
            float b0 = sBias[col], b1 = sBias[col + 1];
            #pragma unroll
            for (int half = 0; half < 2; half++) {
                int r = row0 + warpM * 64 + mt * 16 + g + half * 8;
                if (r < N_NODES) {
                    float v0 = acc[mt][nt][half * 2 + 0] + b0;
                    float v1 = acc[mt][nt][half * 2 + 1] + b1;
                    if (doRelu) { v0 = fmaxf(v0, 0.f); v1 = fmaxf(v1, 0.f); }
                    *(uint32_t*)(hOutHi + (size_t)r * 128 + col) = pack_hi2(v0, v1);
                    *(uint32_t*)(hOutLo + (size_t)r * 128 + col) = pack_lo2(v0, v1);
                }
            }
        }
    }
}

// ---------------- global_add_pool (+ state cleanup for next replay) ----------------
__global__ void k_pool(const int* __restrict__ batch) {
    int w = (blockIdx.x * blockDim.x + threadIdx.x) >> 5;
    int lane = threadIdx.x & 31;
    if (w >= N_NODES) return;
    int g = batch[w];
    int c = lane * 4;
    uint2 hh = *(const uint2*)(g_fh1 + (size_t)w * HID + c);
    uint2 ll = *(const uint2*)(g_fl1 + (size_t)w * HID + c);
    float2 h0 = up2(hh.x), h1 = up2(hh.y);
    float2 l0 = up2(ll.x), l1 = up2(ll.y);
    atomicAdd(&g_pooled[g * HID + c + 0], h0.x + l0.x);
    atomicAdd(&g_pooled[g * HID + c + 1], h0.y + l0.y);
    atomicAdd(&g_pooled[g * HID + c + 2], h1.x + l1.x);
    atomicAdd(&g_pooled[g * HID + c + 3], h1.y + l1.y);
    if (lane == 0) { g_deg[w] = 0; g_cursor[w] = 0; }
}

// ---------------- output head (+ zero pooled for next replay) ----------------
__global__ void k_final(const float* __restrict__ Wout,
                        const float* __restrict__ bout,
                        float* __restrict__ out) {
    int w = (blockIdx.x * blockDim.x + threadIdx.x) >> 5;
    int lane = threadIdx.x & 31;
    if (w >= N_GRAPHS) return;
    float s0 = 0.f, s1 = 0.f;
    #pragma unroll
    for (int i = 0; i < 4; i++) {
        int k = lane * 4 + i;
        float pv = g_pooled[w * HID + k];
        s0 += pv * Wout[k * 2 + 0];
        s1 += pv * Wout[k * 2 + 1];
    }
    #pragma unroll
    for (int i = 0; i < 4; i++) g_pooled[w * HID + lane * 4 + i] = 0.0f;
    #pragma unroll
    for (int off = 16; off; off >>= 1) {
        s0 += __shfl_xor_sync(0xFFFFFFFFu, s0, off);
        s1 += __shfl_xor_sync(0xFFFFFFFFu, s1, off);
    }
    if (lane == 0) {
        out[w * 2 + 0] = s0 + bout[0];
        out[w * 2 + 1] = s1 + bout[1];
    }
}

// ---------------- launch ----------------
extern "C" void kernel_launch(void* const* d_in, const int* in_sizes, int n_in,
                              void* d_out, int out_size) {
    const float* x     = (const float*)d_in[0];
    const int*   ei    = (const int*)d_in[1];
    const int*   src   = ei;
    const int*   dst   = ei + N_EDGES;
    const int*   batch = (const int*)d_in[2];
    const float* Wl    = (const float*)d_in[3];
    const float* Wr    = (const float*)d_in[4];
    const float* bl    = (const float*)d_in[5];
    const float* Wout  = (const float*)d_in[6];
    const float* bout  = (const float*)d_in[7];
    float* out = (float*)d_out;

    __nv_bfloat16 *wt, *fh0, *fl0, *fh1, *fl1;
    cudaGetSymbolAddress((void**)&wt, g_wt);
    cudaGetSymbolAddress((void**)&fh0, g_fh0);
    cudaGetSymbolAddress((void**)&fl0, g_fl0);
    cudaGetSymbolAddress((void**)&fh1, g_fh1);
    cudaGetSymbolAddress((void**)&fl1, g_fl1);

    static bool attr_done = false;
    if (!attr_done) {
        cudaFuncSetAttribute(k_layer, cudaFuncAttributeMaxDynamicSharedMemorySize, LAYER_SMEM);
        attr_done = true;
    }

    // launch 1-3: CSR build + prep (deg/cursor/pooled are 0 at entry every replay)
    k_pre<<<(N_NODES * HID / 4 + 255) / 256, 256>>>(dst, x, Wl, Wr);
    k_scan<<<(N_NODES + 1023) / 1024, 1024>>>();
    k_fill<<<(N_EDGES + 255) / 256, 256>>>(src, dst);

    // launches 4-10: fused layers (ping-pong buffers; x split lives in buf0)
    const int GG = (N_NODES + 127) / 128;  // 391
    for (int i = 0; i < N_LAYERS; i++) {
        const __nv_bfloat16* inHi = (i & 1) ? fh1 : fh0;
        const __nv_bfloat16* inLo = (i & 1) ? fl1 : fl0;
        __nv_bfloat16* outHi = (i & 1) ? fh0 : fh1;
        __nv_bfloat16* outLo = (i & 1) ? fl0 : fl1;
        k_layer<<<GG, 256, LAYER_SMEM>>>(inHi, inLo, outHi, outLo,
                                         wt + (size_t)i * 65536,
                                         bl + (size_t)i * HID,
                                         (i < N_LAYERS - 1) ? 1 : 0);
    }

    k_pool<<<(N_NODES * 32 + 255) / 256, 256>>>(batch);
    k_final<<<(N_GRAPHS * 32 + 255) / 256, 256>>>(Wout, bout, out);
}

// round 7
// speedup vs baseline: 2.1584x; 2.1584x over previous
#include <cuda_runtime.h>
#include <cuda_bf16.h>
#include <cstdint>

#define N_NODES 50000
#define N_EDGES 800000
#define HID 128
#define N_LAYERS 7
#define N_GRAPHS 500

// ---------------- scratch (device globals; zero-init at module load) ----------------
__device__ __nv_bfloat16 g_fh0[N_NODES * HID];   // feature ping-pong buffers (hi/lo split)
__device__ __nv_bfloat16 g_fl0[N_NODES * HID];
__device__ __nv_bfloat16 g_fh1[N_NODES * HID];
__device__ __nv_bfloat16 g_fl1[N_NODES * HID];
__device__ __nv_bfloat16 g_ah[N_NODES * HID];    // aggregated neighbors (split)
__device__ __nv_bfloat16 g_al[N_NODES * HID];
__device__ __nv_bfloat16 g_wt[N_LAYERS * 65536]; // [layer][hi nxk | lo nxk], n=128, k=256
__device__ float g_pooled[N_GRAPHS * HID];       // zeroed by k_final each replay
__device__ float g_invdeg[N_NODES];
__device__ int   g_deg[N_NODES];                 // zeroed by k_pool each replay
__device__ int   g_rowptr[N_NODES + 1];
__device__ int   g_cursor[N_NODES];              // zeroed by k_pool each replay
__device__ int   g_col[N_EDGES];

// ---------------- helpers ----------------
__device__ __forceinline__ uint32_t smem_u32(const void* p) {
    uint32_t a;
    asm("{ .reg .u64 t; cvta.to.shared.u64 t, %1; cvt.u32.u64 %0, t; }" : "=r"(a) : "l"(p));
    return a;
}
__device__ __forceinline__ uint32_t pack_hi2(float a, float b) {
    __nv_bfloat162 t = __floats2bfloat162_rn(a, b);
    return *reinterpret_cast<uint32_t*>(&t);
}
__device__ __forceinline__ uint32_t pack_lo2(float a, float b) {
    float ra = a - __bfloat162float(__float2bfloat16_rn(a));
    float rb = b - __bfloat162float(__float2bfloat16_rn(b));
    __nv_bfloat162 t = __floats2bfloat162_rn(ra, rb);
    return *reinterpret_cast<uint32_t*>(&t);
}
__device__ __forceinline__ float2 up2(uint32_t u) {
    __nv_bfloat162 b = *reinterpret_cast<__nv_bfloat162*>(&u);
    return __bfloat1622float2(b);
}
__device__ __forceinline__ void ldsm_x4(uint32_t* r, uint32_t addr) {
    asm volatile("ldmatrix.sync.aligned.m8n8.x4.shared.b16 {%0,%1,%2,%3}, [%4];"
                 : "=r"(r[0]), "=r"(r[1]), "=r"(r[2]), "=r"(r[3]) : "r"(addr));
}
__device__ __forceinline__ void ldsm_x2(uint32_t* r, uint32_t addr) {
    asm volatile("ldmatrix.sync.aligned.m8n8.x2.shared.b16 {%0,%1}, [%2];"
                 : "=r"(r[0]), "=r"(r[1]) : "r"(addr));
}
__device__ __forceinline__ void mma_bf16(float* c, const uint32_t* a, const uint32_t* b) {
    asm volatile("mma.sync.aligned.m16n8k16.row.col.f32.bf16.bf16.f32 "
                 "{%0,%1,%2,%3}, {%4,%5,%6,%7}, {%8,%9}, {%0,%1,%2,%3};"
                 : "+f"(c[0]), "+f"(c[1]), "+f"(c[2]), "+f"(c[3])
                 : "r"(a[0]), "r"(a[1]), "r"(a[2]), "r"(a[3]), "r"(b[0]), "r"(b[1]));
}
__device__ __forceinline__ void cp16(uint32_t smaddr, const void* gaddr) {
    asm volatile("cp.async.cg.shared.global [%0], [%1], 16;" :: "r"(smaddr), "l"(gaddr));
}
__device__ __forceinline__ void cp_commit() { asm volatile("cp.async.commit_group;"); }
template <int N>
__device__ __forceinline__ void cp_wait() { asm volatile("cp.async.wait_group %0;" :: "n"(N)); }

// ---------------- launch 1: hist + weight prep + x split ----------------
__global__ void k_pre(const int* __restrict__ dst, const float* __restrict__ x,
                      const float* __restrict__ Wl, const float* __restrict__ Wr) {
    int i = blockIdx.x * blockDim.x + threadIdx.x;
    if (i < N_EDGES) atomicAdd(&g_deg[dst[i]], 1);
    if (i < N_LAYERS * 32768) {
        int l = i >> 15;
        int r = i & 32767;
        int n = r >> 8;
        int k = r & 255;
        float w = (k < 128) ? Wl[((size_t)l * 128 + k) * 128 + n]
                            : Wr[((size_t)l * 128 + (k - 128)) * 128 + n];
        __nv_bfloat16 hb = __float2bfloat16_rn(w);
        float lf = w - __bfloat162float(hb);
        size_t bo = (size_t)l * 65536;
        g_wt[bo + (size_t)n * 256 + k] = hb;
        g_wt[bo + 32768 + (size_t)n * 256 + k] = __float2bfloat16_rn(lf);
    }
    if (i < N_NODES * HID / 4) {
        float4 v = *(const float4*)(x + (size_t)i * 4);
        uint2 h, l;
        h.x = pack_hi2(v.x, v.y); h.y = pack_hi2(v.z, v.w);
        l.x = pack_lo2(v.x, v.y); l.y = pack_lo2(v.z, v.w);
        *(uint2*)(g_fh0 + (size_t)i * 4) = h;
        *(uint2*)(g_fl0 + (size_t)i * 4) = l;
    }
}

// ---------------- launch 2: single-launch scan (redundant block prefix) ----------------
__global__ void k_scan() {
    __shared__ int s[1024];
    __shared__ int wsum[32];
    __shared__ int s_off;
    int b = blockIdx.x, t = threadIdx.x;
    int local = 0;
    for (int i = t; i < b * 1024; i += 1024) local += g_deg[i];
    #pragma unroll
    for (int o = 16; o; o >>= 1) local += __shfl_xor_sync(0xFFFFFFFFu, local, o);
    if ((t & 31) == 0) wsum[t >> 5] = local;
    __syncthreads();
    if (t == 0) {
        int o = 0;
        #pragma unroll
        for (int w = 0; w < 32; w++) o += wsum[w];
        s_off = o;
    }
    __syncthreads();
    int offset = s_off;
    int idx = b * 1024 + t;
    int v = (idx < N_NODES) ? g_deg[idx] : 0;
    s[t] = v;
    __syncthreads();
    #pragma unroll
    for (int off = 1; off < 1024; off <<= 1) {
        int u = (t >= off) ? s[t - off] : 0;
        __syncthreads();
        s[t] += u;
        __syncthreads();
    }
    if (idx < N_NODES) {
        g_rowptr[idx + 1] = offset + s[t];
        g_invdeg[idx] = 1.0f / (float)(v > 0 ? v : 1);
    }
    if (b == 0 && t == 0) g_rowptr[0] = 0;
}

// ---------------- launch 3: CSR fill ----------------
__global__ void k_fill(const int* __restrict__ src, const int* __restrict__ dst) {
    int e = blockIdx.x * blockDim.x + threadIdx.x;
    if (e < N_EDGES) {
        int d = dst[e];
        int p = atomicAdd(&g_cursor[d], 1);
        g_col[g_rowptr[d] + p] = src[e];
    }
}

// ---------------- neighbor mean aggregation: warp/node, half-warp hi|lo, 16B lanes ----------------
__global__ void k_agg(const __nv_bfloat16* __restrict__ hInHi,
                      const __nv_bfloat16* __restrict__ hInLo) {
    int w = (blockIdx.x * blockDim.x + threadIdx.x) >> 5;
    int lane = threadIdx.x & 31;
    if (w >= N_NODES) return;
    int beg = g_rowptr[w], end = g_rowptr[w + 1];

    const char* src = (const char*)((lane < 16) ? hInHi : hInLo);
    int colB = (lane & 15) * 16;                 // byte offset in 256B row

    float a0 = 0.f, a1 = 0.f, a2 = 0.f, a3 = 0.f;
    float a4 = 0.f, a5 = 0.f, a6 = 0.f, a7 = 0.f;
    int e = beg;
    for (; e + 2 <= end; e += 2) {
        int s0 = g_col[e], s1 = g_col[e + 1];
        uint4 v0 = *(const uint4*)(src + (size_t)s0 * 256 + colB);
        uint4 v1 = *(const uint4*)(src + (size_t)s1 * 256 + colB);
        float2 p;
        p = up2(v0.x); a0 += p.x; a1 += p.y;
        p = up2(v0.y); a2 += p.x; a3 += p.y;
        p = up2(v0.z); a4 += p.x; a5 += p.y;
        p = up2(v0.w); a6 += p.x; a7 += p.y;
        p = up2(v1.x); a0 += p.x; a1 += p.y;
        p = up2(v1.y); a2 += p.x; a3 += p.y;
        p = up2(v1.z); a4 += p.x; a5 += p.y;
        p = up2(v1.w); a6 += p.x; a7 += p.y;
    }
    if (e < end) {
        int s0 = g_col[e];
        uint4 v0 = *(const uint4*)(src + (size_t)s0 * 256 + colB);
        float2 p;
        p = up2(v0.x); a0 += p.x; a1 += p.y;
        p = up2(v0.y); a2 += p.x; a3 += p.y;
        p = up2(v0.z); a4 += p.x; a5 += p.y;
        p = up2(v0.w); a6 += p.x; a7 += p.y;
    }
    // combine lo-half into hi-half lanes
    a0 += __shfl_down_sync(0xFFFFFFFFu, a0, 16);
    a1 += __shfl_down_sync(0xFFFFFFFFu, a1, 16);
    a2 += __shfl_down_sync(0xFFFFFFFFu, a2, 16);
    a3 += __shfl_down_sync(0xFFFFFFFFu, a3, 16);
    a4 += __shfl_down_sync(0xFFFFFFFFu, a4, 16);
    a5 += __shfl_down_sync(0xFFFFFFFFu, a5, 16);
    a6 += __shfl_down_sync(0xFFFFFFFFu, a6, 16);
    a7 += __shfl_down_sync(0xFFFFFFFFu, a7, 16);

    if (lane < 16) {
        float sc = g_invdeg[w];
        a0 *= sc; a1 *= sc; a2 *= sc; a3 *= sc;
        a4 *= sc; a5 *= sc; a6 *= sc; a7 *= sc;
        uint4 hh, ll;
        hh.x = pack_hi2(a0, a1); hh.y = pack_hi2(a2, a3);
        hh.z = pack_hi2(a4, a5); hh.w = pack_hi2(a6, a7);
        ll.x = pack_lo2(a0, a1); ll.y = pack_lo2(a2, a3);
        ll.z = pack_lo2(a4, a5); ll.w = pack_lo2(a6, a7);
        size_t o = (size_t)w * HID + lane * 8;
        *(uint4*)(g_ah + o) = hh;
        *(uint4*)(g_al + o) = ll;
    }
}

// ---------------- HMMA fused SAGE GEMM (512 thr, cp.async double-buffered) ----------------
// out[128,128] = [agg | h] (K=256, split-bf16) @ Wt (split-bf16) + b, fp32 accum.
// D = Ahi*Bhi + Ahi*Blo + Alo*Bhi.  16 warps, warp tile 32x32.
#define RS 40
#define CTB (128 * RS * 2)             // 10240 B per tile
#define GEMM_SMEM (8 * CTB)            // 81920 B

__global__ void __launch_bounds__(512, 1) k_gemm(
    const __nv_bfloat16* __restrict__ hInHi, const __nv_bfloat16* __restrict__ hInLo,
    __nv_bfloat16* __restrict__ hOutHi, __nv_bfloat16* __restrict__ hOutLo,
    const __nv_bfloat16* __restrict__ wt,
    const float* __restrict__ bias,
    int doRelu)
{
    extern __shared__ __align__(16) char dsm[];
    __shared__ float sBias[128];

    int t = threadIdx.x;
    int lane = t & 31;
    int wid = t >> 5;
    int warpM = wid & 3;       // 0..3 -> rows 32*warpM
    int warpN = wid >> 2;      // 0..3 -> cols 32*warpN
    int row0 = blockIdx.x * 128;
    uint32_t dsb = smem_u32(dsm);

    if (t < 128) sBias[t] = bias[t];

    int srow = t >> 2, sc16 = t & 3;   // 512 threads = 128 rows x 4 16B-chunks
    int srg = row0 + srow;
    if (srg > N_NODES - 1) srg = N_NODES - 1;
    uint32_t smoff = (uint32_t)(srow * RS + sc16 * 8) * 2;

    auto stage = [&](int c8, int buf) {
        const char* srcHi = (const char*)((c8 < 4) ? g_ah : hInHi);
        const char* srcLo = (const char*)((c8 < 4) ? g_al : hInLo);
        uint32_t base = dsb + buf * 4 * CTB;
        size_t ab = (size_t)srg * 256 + (c8 & 3) * 64 + sc16 * 16;
        cp16(base + smoff,           srcHi + ab);
        cp16(base + CTB + smoff,     srcLo + ab);
        size_t wb = (size_t)srow * 512 + (size_t)c8 * 64 + sc16 * 16;
        cp16(base + 2 * CTB + smoff, (const char*)wt + wb);
        cp16(base + 3 * CTB + smoff, (const char*)wt + 65536 + wb);
        cp_commit();
    };

    float acc[2][4][4];
    #pragma unroll
    for (int i = 0; i < 2; i++)
        #pragma unroll
        for (int j = 0; j < 4; j++)
            #pragma unroll
            for (int q = 0; q < 4; q++) acc[i][j][q] = 0.0f;

    stage(0, 0);

    for (int c8 = 0; c8 < 8; c8++) {
        int buf = c8 & 1;
        if (c8 < 7) { stage(c8 + 1, buf ^ 1); cp_wait<1>(); }
        else        { cp_wait<0>(); }
        __syncthreads();

        uint32_t bAh = dsb + buf * 4 * CTB;
        uint32_t bAl = bAh + CTB;
        uint32_t bBh = bAh + 2 * CTB;
        uint32_t bBl = bAh + 3 * CTB;

        #pragma unroll
        for (int kk = 0; kk < 2; kk++) {
            uint32_t ah[2][4], al[2][4], bh[4][2], bl[4][2];
            int ar = warpM * 32 + (lane & 15);
            int akc = kk * 16 + (lane >> 4) * 8;
            #pragma unroll
            for (int mt = 0; mt < 2; mt++) {
                uint32_t off = (uint32_t)((ar + mt * 16) * RS + akc) * 2;
                ldsm_x4(ah[mt], bAh + off);
                ldsm_x4(al[mt], bAl + off);
            }
            int br = warpN * 32 + (lane & 7);
            int bkc = kk * 16 + ((lane >> 3) & 1) * 8;
            #pragma unroll
            for (int nt = 0; nt < 4; nt++) {
                uint32_t off = (uint32_t)((br + nt * 8) * RS + bkc) * 2;
                ldsm_x2(bh[nt], bBh + off);
                ldsm_x2(bl[nt], bBl + off);
            }
            #pragma unroll
            for (int mt = 0; mt < 2; mt++)
                #pragma unroll
                for (int nt = 0; nt < 4; nt++) {
                    mma_bf16(acc[mt][nt], ah[mt], bh[nt]);
                    mma_bf16(acc[mt][nt], ah[mt], bl[nt]);
                    mma_bf16(acc[mt][nt], al[mt], bh[nt]);
                }
        }
        __syncthreads();
    }

    // ---- epilogue ----
    int g = lane >> 2;
    int cc = (lane & 3) * 2;
    #pragma unroll
    for (int mt = 0; mt < 2; mt++) {
        #pragma unroll
        for (int nt = 0; nt < 4; nt++) {
            int col = warpN * 32 + nt * 8 + cc;
            float b0 = sBias[col], b1 = sBias[col + 1];
            #pragma unroll
            for (int half = 0; half < 2; half++) {
                int r = row0 + warpM * 32 + mt * 16 + g + half * 8;
                if (r < N_NODES) {
                    float v0 = acc[mt][nt][half * 2 + 0] + b0;
                    float v1 = acc[mt][nt][half * 2 + 1] + b1;
                    if (doRelu) { v0 = fmaxf(v0, 0.f); v1 = fmaxf(v1, 0.f); }
                    *(uint32_t*)(hOutHi + (size_t)r * 128 + col) = pack_hi2(v0, v1);
                    *(uint32_t*)(hOutLo + (size_t)r * 128 + col) = pack_lo2(v0, v1);
                }
            }
        }
    }
}

// ---------------- global_add_pool (+ state cleanup for next replay) ----------------
__global__ void k_pool(const int* __restrict__ batch) {
    int w = (blockIdx.x * blockDim.x + threadIdx.x) >> 5;
    int lane = threadIdx.x & 31;
    if (w >= N_NODES) return;
    int g = batch[w];
    int c = lane * 4;
    uint2 hh = *(const uint2*)(g_fh1 + (size_t)w * HID + c);
    uint2 ll = *(const uint2*)(g_fl1 + (size_t)w * HID + c);
    float2 h0 = up2(hh.x), h1 = up2(hh.y);
    float2 l0 = up2(ll.x), l1 = up2(ll.y);
    atomicAdd(&g_pooled[g * HID + c + 0], h0.x + l0.x);
    atomicAdd(&g_pooled[g * HID + c + 1], h0.y + l0.y);
    atomicAdd(&g_pooled[g * HID + c + 2], h1.x + l1.x);
    atomicAdd(&g_pooled[g * HID + c + 3], h1.y + l1.y);
    if (lane == 0) { g_deg[w] = 0; g_cursor[w] = 0; }
}

// ---------------- output head (+ zero pooled for next replay) ----------------
__global__ void k_final(const float* __restrict__ Wout,
                        const float* __restrict__ bout,
                        float* __restrict__ out) {
    int w = (blockIdx.x * blockDim.x + threadIdx.x) >> 5;
    int lane = threadIdx.x & 31;
    if (w >= N_GRAPHS) return;
    float s0 = 0.f, s1 = 0.f;
    #pragma unroll
    for (int i = 0; i < 4; i++) {
        int k = lane * 4 + i;
        float pv = g_pooled[w * HID + k];
        s0 += pv * Wout[k * 2 + 0];
        s1 += pv * Wout[k * 2 + 1];
    }
    #pragma unroll
    for (int i = 0; i < 4; i++) g_pooled[w * HID + lane * 4 + i] = 0.0f;
    #pragma unroll
    for (int off = 16; off; off >>= 1) {
        s0 += __shfl_xor_sync(0xFFFFFFFFu, s0, off);
        s1 += __shfl_xor_sync(0xFFFFFFFFu, s1, off);
    }
    if (lane == 0) {
        out[w * 2 + 0] = s0 + bout[0];
        out[w * 2 + 1] = s1 + bout[1];
    }
}

// ---------------- launch ----------------
extern "C" void kernel_launch(void* const* d_in, const int* in_sizes, int n_in,
                              void* d_out, int out_size) {
    const float* x     = (const float*)d_in[0];
    const int*   ei    = (const int*)d_in[1];
    const int*   src   = ei;
    const int*   dst   = ei + N_EDGES;
    const int*   batch = (const int*)d_in[2];
    const float* Wl    = (const float*)d_in[3];
    const float* Wr    = (const float*)d_in[4];
    const float* bl    = (const float*)d_in[5];
    const float* Wout  = (const float*)d_in[6];
    const float* bout  = (const float*)d_in[7];
    float* out = (float*)d_out;

    __nv_bfloat16 *wt, *fh0, *fl0, *fh1, *fl1;
    cudaGetSymbolAddress((void**)&wt, g_wt);
    cudaGetSymbolAddress((void**)&fh0, g_fh0);
    cudaGetSymbolAddress((void**)&fl0, g_fl0);
    cudaGetSymbolAddress((void**)&fh1, g_fh1);
    cudaGetSymbolAddress((void**)&fl1, g_fl1);

    static bool attr_done = false;
    if (!attr_done) {
        cudaFuncSetAttribute(k_gemm, cudaFuncAttributeMaxDynamicSharedMemorySize, GEMM_SMEM);
        attr_done = true;
    }

    k_pre<<<(N_NODES * HID / 4 + 255) / 256, 256>>>(dst, x, Wl, Wr);
    k_scan<<<(N_NODES + 1023) / 1024, 1024>>>();
    k_fill<<<(N_EDGES + 255) / 256, 256>>>(src, dst);

    const int GG = (N_NODES + 127) / 128;  // 391
    for (int i = 0; i < N_LAYERS; i++) {
        const __nv_bfloat16* inHi = (i & 1) ? fh1 : fh0;
        const __nv_bfloat16* inLo = (i & 1) ? fl1 : fl0;
        __nv_bfloat16* outHi = (i & 1) ? fh0 : fh1;
        __nv_bfloat16* outLo = (i & 1) ? fl0 : fl1;
        k_agg<<<(N_NODES * 32 + 255) / 256, 256>>>(inHi, inLo);
        k_gemm<<<GG, 512, GEMM_SMEM>>>(inHi, inLo, outHi, outLo,
                                       wt + (size_t)i * 65536,
                                       bl + (size_t)i * HID,
                                       (i < N_LAYERS - 1) ? 1 : 0);
    }

    k_pool<<<(N_NODES * 32 + 255) / 256, 256>>>(batch);
    k_final<<<(N_GRAPHS * 32 + 255) / 256, 256>>>(Wout, bout, out);
}

// round 8
// speedup vs baseline: 2.3064x; 1.0686x over previous
#include <cuda_runtime.h>
#include <cuda_bf16.h>
#include <cstdint>

#define N_NODES 50000
#define N_EDGES 800000
#define HID 128
#define N_LAYERS 7
#define N_GRAPHS 500

// ---------------- scratch (device globals; zero-init at module load) ----------------
__device__ float g_f[N_NODES * HID];             // fp32 features (for gather; in-place per layer)
__device__ __nv_bfloat16 g_hh[N_NODES * HID];    // split h (GEMM A chunks 4-7; in-place)
__device__ __nv_bfloat16 g_hl[N_NODES * HID];
__device__ __nv_bfloat16 g_ah[N_NODES * HID];    // split aggregated neighbors (GEMM A chunks 0-3)
__device__ __nv_bfloat16 g_al[N_NODES * HID];
__device__ __nv_bfloat16 g_wt[N_LAYERS * 65536]; // [layer][hi nxk | lo nxk], n=128, k=256
__device__ float g_pooled[N_GRAPHS * HID];       // zeroed by k_final each replay
__device__ float g_invdeg[N_NODES];
__device__ int   g_deg[N_NODES];                 // zeroed by k_pool each replay
__device__ int   g_rowptr[N_NODES + 1];
__device__ int   g_cursor[N_NODES];              // zeroed by k_pool each replay
__device__ int   g_col[N_EDGES];

// ---------------- helpers ----------------
__device__ __forceinline__ uint32_t smem_u32(const void* p) {
    uint32_t a;
    asm("{ .reg .u64 t; cvta.to.shared.u64 t, %1; cvt.u32.u64 %0, t; }" : "=r"(a) : "l"(p));
    return a;
}
__device__ __forceinline__ uint32_t pack_hi2(float a, float b) {
    __nv_bfloat162 t = __floats2bfloat162_rn(a, b);
    return *reinterpret_cast<uint32_t*>(&t);
}
__device__ __forceinline__ uint32_t pack_lo2(float a, float b) {
    float ra = a - __bfloat162float(__float2bfloat16_rn(a));
    float rb = b - __bfloat162float(__float2bfloat16_rn(b));
    __nv_bfloat162 t = __floats2bfloat162_rn(ra, rb);
    return *reinterpret_cast<uint32_t*>(&t);
}
__device__ __forceinline__ void ldsm_x4(uint32_t* r, uint32_t addr) {
    asm volatile("ldmatrix.sync.aligned.m8n8.x4.shared.b16 {%0,%1,%2,%3}, [%4];"
                 : "=r"(r[0]), "=r"(r[1]), "=r"(r[2]), "=r"(r[3]) : "r"(addr));
}
__device__ __forceinline__ void ldsm_x2(uint32_t* r, uint32_t addr) {
    asm volatile("ldmatrix.sync.aligned.m8n8.x2.shared.b16 {%0,%1}, [%2];"
                 : "=r"(r[0]), "=r"(r[1]) : "r"(addr));
}
__device__ __forceinline__ void mma_bf16(float* c, const uint32_t* a, const uint32_t* b) {
    asm volatile("mma.sync.aligned.m16n8k16.row.col.f32.bf16.bf16.f32 "
                 "{%0,%1,%2,%3}, {%4,%5,%6,%7}, {%8,%9}, {%0,%1,%2,%3};"
                 : "+f"(c[0]), "+f"(c[1]), "+f"(c[2]), "+f"(c[3])
                 : "r"(a[0]), "r"(a[1]), "r"(a[2]), "r"(a[3]), "r"(b[0]), "r"(b[1]));
}
__device__ __forceinline__ void cp16(uint32_t smaddr, const void* gaddr) {
    asm volatile("cp.async.cg.shared.global [%0], [%1], 16;" :: "r"(smaddr), "l"(gaddr));
}
__device__ __forceinline__ void cp_commit() { asm volatile("cp.async.commit_group;"); }
template <int N>
__device__ __forceinline__ void cp_wait() { asm volatile("cp.async.wait_group %0;" :: "n"(N)); }

// ---------------- launch 1: hist + weight prep ----------------
__global__ void k_pre(const int* __restrict__ dst,
                      const float* __restrict__ Wl, const float* __restrict__ Wr) {
    int i = blockIdx.x * blockDim.x + threadIdx.x;
    if (i < N_EDGES) atomicAdd(&g_deg[dst[i]], 1);
    if (i < N_LAYERS * 32768) {
        int l = i >> 15;
        int r = i & 32767;
        int n = r >> 8;
        int k = r & 255;
        float w = (k < 128) ? Wl[((size_t)l * 128 + k) * 128 + n]
                            : Wr[((size_t)l * 128 + (k - 128)) * 128 + n];
        __nv_bfloat16 hb = __float2bfloat16_rn(w);
        float lf = w - __bfloat162float(hb);
        size_t bo = (size_t)l * 65536;
        g_wt[bo + (size_t)n * 256 + k] = hb;
        g_wt[bo + 32768 + (size_t)n * 256 + k] = __float2bfloat16_rn(lf);
    }
}

// ---------------- launch 2: single-launch scan (redundant block prefix) ----------------
__global__ void k_scan() {
    __shared__ int s[1024];
    __shared__ int wsum[32];
    __shared__ int s_off;
    int b = blockIdx.x, t = threadIdx.x;
    int local = 0;
    for (int i = t; i < b * 1024; i += 1024) local += g_deg[i];
    #pragma unroll
    for (int o = 16; o; o >>= 1) local += __shfl_xor_sync(0xFFFFFFFFu, local, o);
    if ((t & 31) == 0) wsum[t >> 5] = local;
    __syncthreads();
    if (t == 0) {
        int o = 0;
        #pragma unroll
        for (int w = 0; w < 32; w++) o += wsum[w];
        s_off = o;
    }
    __syncthreads();
    int offset = s_off;
    int idx = b * 1024 + t;
    int v = (idx < N_NODES) ? g_deg[idx] : 0;
    s[t] = v;
    __syncthreads();
    #pragma unroll
    for (int off = 1; off < 1024; off <<= 1) {
        int u = (t >= off) ? s[t - off] : 0;
        __syncthreads();
        s[t] += u;
        __syncthreads();
    }
    if (idx < N_NODES) {
        g_rowptr[idx + 1] = offset + s[t];
        g_invdeg[idx] = 1.0f / (float)(v > 0 ? v : 1);
    }
    if (b == 0 && t == 0) g_rowptr[0] = 0;
}

// ---------------- launch 3: CSR fill ----------------
__global__ void k_fill(const int* __restrict__ src, const int* __restrict__ dst) {
    int e = blockIdx.x * blockDim.x + threadIdx.x;
    if (e < N_EDGES) {
        int d = dst[e];
        int p = atomicAdd(&g_cursor[d], 1);
        g_col[g_rowptr[d] + p] = src[e];
    }
}

// ---------------- launch 4: split x into bf16 hi/lo (GEMM-0 h-half) ----------------
__global__ void k_xsplit(const float* __restrict__ x) {
    int i = blockIdx.x * blockDim.x + threadIdx.x;
    if (i >= N_NODES * HID / 4) return;
    float4 v = *(const float4*)(x + (size_t)i * 4);
    uint2 h, l;
    h.x = pack_hi2(v.x, v.y); h.y = pack_hi2(v.z, v.w);
    l.x = pack_lo2(v.x, v.y); l.y = pack_lo2(v.z, v.w);
    *(uint2*)(g_hh + (size_t)i * 4) = h;
    *(uint2*)(g_hl + (size_t)i * 4) = l;
}

// ---------------- neighbor mean aggregation: warp/node, fp32 gather ----------------
// lane covers cols [lane*4, lane*4+4): 1 LDG.128 + 4 FADD per edge, no conversions.
__global__ void k_agg(const float* __restrict__ hIn) {
    int w = (blockIdx.x * blockDim.x + threadIdx.x) >> 5;
    int lane = threadIdx.x & 31;
    if (w >= N_NODES) return;
    int beg = g_rowptr[w], end = g_rowptr[w + 1];
    int c = lane * 4;

    float a0 = 0.f, a1 = 0.f, a2 = 0.f, a3 = 0.f;
    float b0 = 0.f, b1 = 0.f, b2 = 0.f, b3 = 0.f;
    int e = beg;
    for (; e + 2 <= end; e += 2) {
        int s0 = g_col[e], s1 = g_col[e + 1];
        float4 v0 = *(const float4*)(hIn + (size_t)s0 * HID + c);
        float4 v1 = *(const float4*)(hIn + (size_t)s1 * HID + c);
        a0 += v0.x; a1 += v0.y; a2 += v0.z; a3 += v0.w;
        b0 += v1.x; b1 += v1.y; b2 += v1.z; b3 += v1.w;
    }
    if (e < end) {
        int s0 = g_col[e];
        float4 v0 = *(const float4*)(hIn + (size_t)s0 * HID + c);
        a0 += v0.x; a1 += v0.y; a2 += v0.z; a3 += v0.w;
    }
    float sc = g_invdeg[w];
    a0 = (a0 + b0) * sc; a1 = (a1 + b1) * sc;
    a2 = (a2 + b2) * sc; a3 = (a3 + b3) * sc;
    uint2 hh, ll;
    hh.x = pack_hi2(a0, a1); hh.y = pack_hi2(a2, a3);
    ll.x = pack_lo2(a0, a1); ll.y = pack_lo2(a2, a3);
    size_t o = (size_t)w * HID + c;
    *(uint2*)(g_ah + o) = hh;
    *(uint2*)(g_al + o) = ll;
}

// ---------------- HMMA fused SAGE GEMM (512 thr, cp.async double-buffered) ----------------
// out[128,128] = [agg | h] (K=256, split-bf16) @ Wt (split-bf16) + b, fp32 accum.
// D = Ahi*Bhi + Ahi*Blo + Alo*Bhi.  16 warps, warp tile 32x32.
// Epilogue: fp32 -> g_f (for next agg / pool); split bf16 -> g_hh/g_hl (own rows, in-place safe).
#define RS 40
#define CTB (128 * RS * 2)             // 10240 B per tile
#define GEMM_SMEM (8 * CTB)            // 81920 B

__global__ void __launch_bounds__(512, 1) k_gemm(
    const __nv_bfloat16* __restrict__ wt,
    const float* __restrict__ bias,
    int doRelu, int doSplit)
{
    extern __shared__ __align__(16) char dsm[];
    __shared__ float sBias[128];

    int t = threadIdx.x;
    int lane = t & 31;
    int wid = t >> 5;
    int warpM = wid & 3;       // 0..3 -> rows 32*warpM
    int warpN = wid >> 2;      // 0..3 -> cols 32*warpN
    int row0 = blockIdx.x * 128;
    uint32_t dsb = smem_u32(dsm);

    if (t < 128) sBias[t] = bias[t];

    int srow = t >> 2, sc16 = t & 3;   // 512 threads = 128 rows x 4 16B-chunks
    int srg = row0 + srow;
    if (srg > N_NODES - 1) srg = N_NODES - 1;
    uint32_t smoff = (uint32_t)(srow * RS + sc16 * 8) * 2;

    auto stage = [&](int c8, int buf) {
        const char* srcHi = (const char*)((c8 < 4) ? g_ah : g_hh);
        const char* srcLo = (const char*)((c8 < 4) ? g_al : g_hl);
        uint32_t base = dsb + buf * 4 * CTB;
        size_t ab = (size_t)srg * 256 + (c8 & 3) * 64 + sc16 * 16;
        cp16(base + smoff,           srcHi + ab);
        cp16(base + CTB + smoff,     srcLo + ab);
        size_t wb = (size_t)srow * 512 + (size_t)c8 * 64 + sc16 * 16;
        cp16(base + 2 * CTB + smoff, (const char*)wt + wb);
        cp16(base + 3 * CTB + smoff, (const char*)wt + 65536 + wb);
        cp_commit();
    };

    float acc[2][4][4];
    #pragma unroll
    for (int i = 0; i < 2; i++)
        #pragma unroll
        for (int j = 0; j < 4; j++)
            #pragma unroll
            for (int q = 0; q < 4; q++) acc[i][j][q] = 0.0f;

    stage(0, 0);

    for (int c8 = 0; c8 < 8; c8++) {
        int buf = c8 & 1;
        if (c8 < 7) { stage(c8 + 1, buf ^ 1); cp_wait<1>(); }
        else        { cp_wait<0>(); }
        __syncthreads();

        uint32_t bAh = dsb + buf * 4 * CTB;
        uint32_t bAl = bAh + CTB;
        uint32_t bBh = bAh + 2 * CTB;
        uint32_t bBl = bAh + 3 * CTB;

        #pragma unroll
        for (int kk = 0; kk < 2; kk++) {
            uint32_t ah[2][4], al[2][4], bh[4][2], bl[4][2];
            int ar = warpM * 32 + (lane & 15);
            int akc = kk * 16 + (lane >> 4) * 8;
            #pragma unroll
            for (int mt = 0; mt < 2; mt++) {
                uint32_t off = (uint32_t)((ar + mt * 16) * RS + akc) * 2;
                ldsm_x4(ah[mt], bAh + off);
                ldsm_x4(al[mt], bAl + off);
            }
            int br = warpN * 32 + (lane & 7);
            int bkc = kk * 16 + ((lane >> 3) & 1) * 8;
            #pragma unroll
            for (int nt = 0; nt < 4; nt++) {
                uint32_t off = (uint32_t)((br + nt * 8) * RS + bkc) * 2;
                ldsm_x2(bh[nt], bBh + off);
                ldsm_x2(bl[nt], bBl + off);
            }
            #pragma unroll
            for (int mt = 0; mt < 2; mt++)
                #pragma unroll
                for (int nt = 0; nt < 4; nt++) {
                    mma_bf16(acc[mt][nt], ah[mt], bh[nt]);
                    mma_bf16(acc[mt][nt], ah[mt], bl[nt]);
                    mma_bf16(acc[mt][nt], al[mt], bh[nt]);
                }
        }
        __syncthreads();
    }

    // ---- epilogue: bias + relu; write fp32 (always) + split bf16 (if doSplit) ----
    int g = lane >> 2;
    int cc = (lane & 3) * 2;
    #pragma unroll
    for (int mt = 0; mt < 2; mt++) {
        #pragma unroll
        for (int nt = 0; nt < 4; nt++) {
            int col = warpN * 32 + nt * 8 + cc;
            float b0 = sBias[col], b1 = sBias[col + 1];
            #pragma unroll
            for (int half = 0; half < 2; half++) {
                int r = row0 + warpM * 32 + mt * 16 + g + half * 8;
                if (r < N_NODES) {
                    float v0 = acc[mt][nt][half * 2 + 0] + b0;
                    float v1 = acc[mt][nt][half * 2 + 1] + b1;
                    if (doRelu) { v0 = fmaxf(v0, 0.f); v1 = fmaxf(v1, 0.f); }
                    *(float2*)(g_f + (size_t)r * 128 + col) = make_float2(v0, v1);
                    if (doSplit) {
                        *(uint32_t*)(g_hh + (size_t)r * 128 + col) = pack_hi2(v0, v1);
                        *(uint32_t*)(g_hl + (size_t)r * 128 + col) = pack_lo2(v0, v1);
                    }
                }
            }
        }
    }
}

// ---------------- global_add_pool (fp32 read; + state cleanup for next replay) ----------------
__global__ void k_pool(const int* __restrict__ batch) {
    int w = (blockIdx.x * blockDim.x + threadIdx.x) >> 5;
    int lane = threadIdx.x & 31;
    if (w >= N_NODES) return;
    int g = batch[w];
    int c = lane * 4;
    float4 v = *(const float4*)(g_f + (size_t)w * HID + c);
    atomicAdd(&g_pooled[g * HID + c + 0], v.x);
    atomicAdd(&g_pooled[g * HID + c + 1], v.y);
    atomicAdd(&g_pooled[g * HID + c + 2], v.z);
    atomicAdd(&g_pooled[g * HID + c + 3], v.w);
    if (lane == 0) { g_deg[w] = 0; g_cursor[w] = 0; }
}

// ---------------- output head (+ zero pooled for next replay) ----------------
__global__ void k_final(const float* __restrict__ Wout,
                        const float* __restrict__ bout,
                        float* __restrict__ out) {
    int w = (blockIdx.x * blockDim.x + threadIdx.x) >> 5;
    int lane = threadIdx.x & 31;
    if (w >= N_GRAPHS) return;
    float s0 = 0.f, s1 = 0.f;
    #pragma unroll
    for (int i = 0; i < 4; i++) {
        int k = lane * 4 + i;
        float pv = g_pooled[w * HID + k];
        s0 += pv * Wout[k * 2 + 0];
        s1 += pv * Wout[k * 2 + 1];
    }
    #pragma unroll
    for (int i = 0; i < 4; i++) g_pooled[w * HID + lane * 4 + i] = 0.0f;
    #pragma unroll
    for (int off = 16; off; off >>= 1) {
        s0 += __shfl_xor_sync(0xFFFFFFFFu, s0, off);
        s1 += __shfl_xor_sync(0xFFFFFFFFu, s1, off);
    }
    if (lane == 0) {
        out[w * 2 + 0] = s0 + bout[0];
        out[w * 2 + 1] = s1 + bout[1];
    }
}

// ---------------- launch ----------------
extern "C" void kernel_launch(void* const* d_in, const int* in_sizes, int n_in,
                              void* d_out, int out_size) {
    const float* x     = (const float*)d_in[0];
    const int*   ei    = (const int*)d_in[1];
    const int*   src   = ei;
    const int*   dst   = ei + N_EDGES;
    const int*   batch = (const int*)d_in[2];
    const float* Wl    = (const float*)d_in[3];
    const float* Wr    = (const float*)d_in[4];
    const float* bl    = (const float*)d_in[5];
    const float* Wout  = (const float*)d_in[6];
    const float* bout  = (const float*)d_in[7];
    float* out = (float*)d_out;

    __nv_bfloat16* wt;
    float* f;
    cudaGetSymbolAddress((void**)&wt, g_wt);
    cudaGetSymbolAddress((void**)&f, g_f);

    static bool attr_done = false;
    if (!attr_done) {
        cudaFuncSetAttribute(k_gemm, cudaFuncAttributeMaxDynamicSharedMemorySize, GEMM_SMEM);
        attr_done = true;
    }

    // launches 1-4: CSR build + weight/x prep (deg/cursor/pooled are 0 at entry)
    k_pre<<<(N_EDGES + 255) / 256, 256>>>(dst, Wl, Wr);
    k_scan<<<(N_NODES + 1023) / 1024, 1024>>>();
    k_fill<<<(N_EDGES + 255) / 256, 256>>>(src, dst);
    k_xsplit<<<(N_NODES * HID / 4 + 255) / 256, 256>>>(x);

    // layers: agg gathers fp32 (x for layer 0, g_f after), gemm writes g_f + split
    const int GG = (N_NODES + 127) / 128;  // 391
    for (int i = 0; i < N_LAYERS; i++) {
        k_agg<<<(N_NODES * 32 + 255) / 256, 256>>>(i == 0 ? x : f);
        k_gemm<<<GG, 512, GEMM_SMEM>>>(wt + (size_t)i * 65536,
                                       bl + (size_t)i * HID,
                                       (i < N_LAYERS - 1) ? 1 : 0,
                                       (i < N_LAYERS - 1) ? 1 : 0);
    }

    k_pool<<<(N_NODES * 32 + 255) / 256, 256>>>(batch);
    k_final<<<(N_GRAPHS * 32 + 255) / 256, 256>>>(Wout, bout, out);
}

// round 9
// speedup vs baseline: 2.5276x; 1.0959x over previous
#include <cuda_runtime.h>
#include <cuda_bf16.h>
#include <cstdint>

#define N_NODES 50000
#define N_EDGES 800000
#define HID 128
#define N_LAYERS 7
#define N_GRAPHS 500

// ---------------- scratch (device globals; zero-init at module load) ----------------
__device__ float g_f[N_NODES * HID];             // fp32 features (for gather; in-place per layer)
__device__ __nv_bfloat16 g_hh[N_NODES * HID];    // split h (GEMM A chunks 4-7; in-place)
__device__ __nv_bfloat16 g_hl[N_NODES * HID];
__device__ __nv_bfloat16 g_ah[N_NODES * HID];    // split aggregated neighbors (GEMM A chunks 0-3)
__device__ __nv_bfloat16 g_al[N_NODES * HID];
__device__ __nv_bfloat16 g_wt[N_LAYERS * 65536]; // [layer][hi nxk | lo nxk], n=128, k=256
__device__ float g_pooled[N_GRAPHS * HID];       // zeroed by k_final each replay
__device__ float g_invdeg[N_NODES];
__device__ int   g_deg[N_NODES];                 // zeroed by k_pool each replay
__device__ int   g_rowptr[N_NODES + 1];
__device__ int   g_cursor[N_NODES];              // zeroed by k_pool each replay
__device__ int   g_col[N_EDGES];

// ---------------- helpers ----------------
__device__ __forceinline__ uint32_t smem_u32(const void* p) {
    uint32_t a;
    asm("{ .reg .u64 t; cvta.to.shared.u64 t, %1; cvt.u32.u64 %0, t; }" : "=r"(a) : "l"(p));
    return a;
}
__device__ __forceinline__ uint32_t pack_hi2(float a, float b) {
    __nv_bfloat162 t = __floats2bfloat162_rn(a, b);
    return *reinterpret_cast<uint32_t*>(&t);
}
__device__ __forceinline__ uint32_t pack_lo2(float a, float b) {
    float ra = a - __bfloat162float(__float2bfloat16_rn(a));
    float rb = b - __bfloat162float(__float2bfloat16_rn(b));
    __nv_bfloat162 t = __floats2bfloat162_rn(ra, rb);
    return *reinterpret_cast<uint32_t*>(&t);
}
__device__ __forceinline__ void ldsm_x4(uint32_t* r, uint32_t addr) {
    asm volatile("ldmatrix.sync.aligned.m8n8.x4.shared.b16 {%0,%1,%2,%3}, [%4];"
                 : "=r"(r[0]), "=r"(r[1]), "=r"(r[2]), "=r"(r[3]) : "r"(addr));
}
__device__ __forceinline__ void ldsm_x2(uint32_t* r, uint32_t addr) {
    asm volatile("ldmatrix.sync.aligned.m8n8.x2.shared.b16 {%0,%1}, [%2];"
                 : "=r"(r[0]), "=r"(r[1]) : "r"(addr));
}
__device__ __forceinline__ void mma_bf16(float* c, const uint32_t* a, const uint32_t* b) {
    asm volatile("mma.sync.aligned.m16n8k16.row.col.f32.bf16.bf16.f32 "
                 "{%0,%1,%2,%3}, {%4,%5,%6,%7}, {%8,%9}, {%0,%1,%2,%3};"
                 : "+f"(c[0]), "+f"(c[1]), "+f"(c[2]), "+f"(c[3])
                 : "r"(a[0]), "r"(a[1]), "r"(a[2]), "r"(a[3]), "r"(b[0]), "r"(b[1]));
}
__device__ __forceinline__ void cp16(uint32_t smaddr, const void* gaddr) {
    asm volatile("cp.async.cg.shared.global [%0], [%1], 16;" :: "r"(smaddr), "l"(gaddr));
}
__device__ __forceinline__ void cp_commit() { asm volatile("cp.async.commit_group;"); }
template <int N>
__device__ __forceinline__ void cp_wait() { asm volatile("cp.async.wait_group %0;" :: "n"(N)); }

// ---------------- launch 1: hist + weight prep + x split ----------------
__global__ void k_pre(const int* __restrict__ dst, const float* __restrict__ x,
                      const float* __restrict__ Wl, const float* __restrict__ Wr) {
    int i = blockIdx.x * blockDim.x + threadIdx.x;
    if (i < N_EDGES) atomicAdd(&g_deg[dst[i]], 1);
    if (i < N_LAYERS * 32768) {
        int l = i >> 15;
        int r = i & 32767;
        int n = r >> 8;
        int k = r & 255;
        float w = (k < 128) ? Wl[((size_t)l * 128 + k) * 128 + n]
                            : Wr[((size_t)l * 128 + (k - 128)) * 128 + n];
        __nv_bfloat16 hb = __float2bfloat16_rn(w);
        float lf = w - __bfloat162float(hb);
        size_t bo = (size_t)l * 65536;
        g_wt[bo + (size_t)n * 256 + k] = hb;
        g_wt[bo + 32768 + (size_t)n * 256 + k] = __float2bfloat16_rn(lf);
    }
    if (i < N_NODES * HID / 4) {
        float4 v = *(const float4*)(x + (size_t)i * 4);
        uint2 h, l;
        h.x = pack_hi2(v.x, v.y); h.y = pack_hi2(v.z, v.w);
        l.x = pack_lo2(v.x, v.y); l.y = pack_lo2(v.z, v.w);
        *(uint2*)(g_hh + (size_t)i * 4) = h;
        *(uint2*)(g_hl + (size_t)i * 4) = l;
    }
}

// ---------------- launch 2: single-launch scan (redundant block prefix) ----------------
__global__ void k_scan() {
    __shared__ int s[1024];
    __shared__ int wsum[32];
    __shared__ int s_off;
    int b = blockIdx.x, t = threadIdx.x;
    int local = 0;
    for (int i = t; i < b * 1024; i += 1024) local += g_deg[i];
    #pragma unroll
    for (int o = 16; o; o >>= 1) local += __shfl_xor_sync(0xFFFFFFFFu, local, o);
    if ((t & 31) == 0) wsum[t >> 5] = local;
    __syncthreads();
    if (t == 0) {
        int o = 0;
        #pragma unroll
        for (int w = 0; w < 32; w++) o += wsum[w];
        s_off = o;
    }
    __syncthreads();
    int offset = s_off;
    int idx = b * 1024 + t;
    int v = (idx < N_NODES) ? g_deg[idx] : 0;
    s[t] = v;
    __syncthreads();
    #pragma unroll
    for (int off = 1; off < 1024; off <<= 1) {
        int u = (t >= off) ? s[t - off] : 0;
        __syncthreads();
        s[t] += u;
        __syncthreads();
    }
    if (idx < N_NODES) {
        g_rowptr[idx + 1] = offset + s[t];
        g_invdeg[idx] = 1.0f / (float)(v > 0 ? v : 1);
    }
    if (b == 0 && t == 0) g_rowptr[0] = 0;
}

// ---------------- launch 3: CSR fill ----------------
__global__ void k_fill(const int* __restrict__ src, const int* __restrict__ dst) {
    int e = blockIdx.x * blockDim.x + threadIdx.x;
    if (e < N_EDGES) {
        int d = dst[e];
        int p = atomicAdd(&g_cursor[d], 1);
        g_col[g_rowptr[d] + p] = src[e];
    }
}

// ---------------- neighbor mean aggregation: warp/node, fp32 gather ----------------
__global__ void k_agg(const float* __restrict__ hIn) {
    int w = (blockIdx.x * blockDim.x + threadIdx.x) >> 5;
    int lane = threadIdx.x & 31;
    if (w >= N_NODES) return;
    int beg = g_rowptr[w], end = g_rowptr[w + 1];
    int c = lane * 4;

    float a0 = 0.f, a1 = 0.f, a2 = 0.f, a3 = 0.f;
    float b0 = 0.f, b1 = 0.f, b2 = 0.f, b3 = 0.f;
    int e = beg;
    for (; e + 2 <= end; e += 2) {
        int s0 = g_col[e], s1 = g_col[e + 1];
        float4 v0 = *(const float4*)(hIn + (size_t)s0 * HID + c);
        float4 v1 = *(const float4*)(hIn + (size_t)s1 * HID + c);
        a0 += v0.x; a1 += v0.y; a2 += v0.z; a3 += v0.w;
        b0 += v1.x; b1 += v1.y; b2 += v1.z; b3 += v1.w;
    }
    if (e < end) {
        int s0 = g_col[e];
        float4 v0 = *(const float4*)(hIn + (size_t)s0 * HID + c);
        a0 += v0.x; a1 += v0.y; a2 += v0.z; a3 += v0.w;
    }
    float sc = g_invdeg[w];
    a0 = (a0 + b0) * sc; a1 = (a1 + b1) * sc;
    a2 = (a2 + b2) * sc; a3 = (a3 + b3) * sc;
    uint2 hh, ll;
    hh.x = pack_hi2(a0, a1); hh.y = pack_hi2(a2, a3);
    ll.x = pack_lo2(a0, a1); ll.y = pack_lo2(a2, a3);
    size_t o = (size_t)w * HID + c;
    *(uint2*)(g_ah + o) = hh;
    *(uint2*)(g_al + o) = ll;
}

// ---------------- HMMA fused SAGE GEMM (512 thr, 2 CTA/SM, cp.async dbl-buffered) ----------------
// out[128,128] = [agg | h] (K=256, split-bf16) @ Wt (split-bf16) + b, fp32 accum.
// D = Ahi*Bhi + Ahi*Blo + Alo*Bhi.  16 warps, warp tile 32x32.
#define RS 40
#define CTB (128 * RS * 2)             // 10240 B per tile
#define GEMM_SMEM (8 * CTB)            // 81920 B

__global__ void __launch_bounds__(512, 2) k_gemm(
    const __nv_bfloat16* __restrict__ wt,
    const float* __restrict__ bias,
    int doRelu, int doSplit)
{
    extern __shared__ __align__(16) char dsm[];
    __shared__ float sBias[128];

    int t = threadIdx.x;
    int lane = t & 31;
    int wid = t >> 5;
    int warpM = wid & 3;       // 0..3 -> rows 32*warpM
    int warpN = wid >> 2;      // 0..3 -> cols 32*warpN
    int row0 = blockIdx.x * 128;
    uint32_t dsb = smem_u32(dsm);

    if (t < 128) sBias[t] = bias[t];

    int srow = t >> 2, sc16 = t & 3;   // 512 threads = 128 rows x 4 16B-chunks
    int srg = row0 + srow;
    if (srg > N_NODES - 1) srg = N_NODES - 1;
    uint32_t smoff = (uint32_t)(srow * RS + sc16 * 8) * 2;

    auto stage = [&](int c8, int buf) {
        const char* srcHi = (const char*)((c8 < 4) ? g_ah : g_hh);
        const char* srcLo = (const char*)((c8 < 4) ? g_al : g_hl);
        uint32_t base = dsb + buf * 4 * CTB;
        size_t ab = (size_t)srg * 256 + (c8 & 3) * 64 + sc16 * 16;
        cp16(base + smoff,           srcHi + ab);
        cp16(base + CTB + smoff,     srcLo + ab);
        size_t wb = (size_t)srow * 512 + (size_t)c8 * 64 + sc16 * 16;
        cp16(base + 2 * CTB + smoff, (const char*)wt + wb);
        cp16(base + 3 * CTB + smoff, (const char*)wt + 65536 + wb);
        cp_commit();
    };

    float acc[2][4][4];
    #pragma unroll
    for (int i = 0; i < 2; i++)
        #pragma unroll
        for (int j = 0; j < 4; j++)
            #pragma unroll
            for (int q = 0; q < 4; q++) acc[i][j][q] = 0.0f;

    stage(0, 0);

    for (int c8 = 0; c8 < 8; c8++) {
        int buf = c8 & 1;
        if (c8 < 7) { stage(c8 + 1, buf ^ 1); cp_wait<1>(); }
        else        { cp_wait<0>(); }
        __syncthreads();

        uint32_t bAh = dsb + buf * 4 * CTB;
        uint32_t bAl = bAh + CTB;
        uint32_t bBh = bAh + 2 * CTB;
        uint32_t bBl = bAh + 3 * CTB;

        #pragma unroll
        for (int kk = 0; kk < 2; kk++) {
            uint32_t ah[2][4], al[2][4], bf[4][2];
            int ar = warpM * 32 + (lane & 15);
            int akc = kk * 16 + (lane >> 4) * 8;
            #pragma unroll
            for (int mt = 0; mt < 2; mt++) {
                uint32_t off = (uint32_t)((ar + mt * 16) * RS + akc) * 2;
                ldsm_x4(ah[mt], bAh + off);
                ldsm_x4(al[mt], bAl + off);
            }
            int br = warpN * 32 + (lane & 7);
            int bkc = kk * 16 + ((lane >> 3) & 1) * 8;
            // --- Bhi terms: Ahi*Bhi + Alo*Bhi (then bf dead) ---
            #pragma unroll
            for (int nt = 0; nt < 4; nt++) {
                uint32_t off = (uint32_t)((br + nt * 8) * RS + bkc) * 2;
                ldsm_x2(bf[nt], bBh + off);
            }
            #pragma unroll
            for (int mt = 0; mt < 2; mt++)
                #pragma unroll
                for (int nt = 0; nt < 4; nt++) {
                    mma_bf16(acc[mt][nt], ah[mt], bf[nt]);
                    mma_bf16(acc[mt][nt], al[mt], bf[nt]);
                }
            // --- Blo term: Ahi*Blo ---
            #pragma unroll
            for (int nt = 0; nt < 4; nt++) {
                uint32_t off = (uint32_t)((br + nt * 8) * RS + bkc) * 2;
                ldsm_x2(bf[nt], bBl + off);
            }
            #pragma unroll
            for (int mt = 0; mt < 2; mt++)
                #pragma unroll
                for (int nt = 0; nt < 4; nt++)
                    mma_bf16(acc[mt][nt], ah[mt], bf[nt]);
        }
        __syncthreads();
    }

    // ---- epilogue: bias + relu; write fp32 (always) + split bf16 (if doSplit) ----
    int g = lane >> 2;
    int cc = (lane & 3) * 2;
    #pragma unroll
    for (int mt = 0; mt < 2; mt++) {
        #pragma unroll
        for (int nt = 0; nt < 4; nt++) {
            int col = warpN * 32 + nt * 8 + cc;
            float b0 = sBias[col], b1 = sBias[col + 1];
            #pragma unroll
            for (int half = 0; half < 2; half++) {
                int r = row0 + warpM * 32 + mt * 16 + g + half * 8;
                if (r < N_NODES) {
                    float v0 = acc[mt][nt][half * 2 + 0] + b0;
                    float v1 = acc[mt][nt][half * 2 + 1] + b1;
                    if (doRelu) { v0 = fmaxf(v0, 0.f); v1 = fmaxf(v1, 0.f); }
                    *(float2*)(g_f + (size_t)r * 128 + col) = make_float2(v0, v1);
                    if (doSplit) {
                        *(uint32_t*)(g_hh + (size_t)r * 128 + col) = pack_hi2(v0, v1);
                        *(uint32_t*)(g_hl + (size_t)r * 128 + col) = pack_lo2(v0, v1);
                    }
                }
            }
        }
    }
}

// ---------------- global_add_pool (fp32 read; + state cleanup for next replay) ----------------
__global__ void k_pool(const int* __restrict__ batch) {
    int w = (blockIdx.x * blockDim.x + threadIdx.x) >> 5;
    int lane = threadIdx.x & 31;
    if (w >= N_NODES) return;
    int g = batch[w];
    int c = lane * 4;
    float4 v = *(const float4*)(g_f + (size_t)w * HID + c);
    atomicAdd(&g_pooled[g * HID + c + 0], v.x);
    atomicAdd(&g_pooled[g * HID + c + 1], v.y);
    atomicAdd(&g_pooled[g * HID + c + 2], v.z);
    atomicAdd(&g_pooled[g * HID + c + 3], v.w);
    if (lane == 0) { g_deg[w] = 0; g_cursor[w] = 0; }
}

// ---------------- output head (+ zero pooled for next replay) ----------------
__global__ void k_final(const float* __restrict__ Wout,
                        const float* __restrict__ bout,
                        float* __restrict__ out) {
    int w = (blockIdx.x * blockDim.x + threadIdx.x) >> 5;
    int lane = threadIdx.x & 31;
    if (w >= N_GRAPHS) return;
    float s0 = 0.f, s1 = 0.f;
    #pragma unroll
    for (int i = 0; i < 4; i++) {
        int k = lane * 4 + i;
        float pv = g_pooled[w * HID + k];
        s0 += pv * Wout[k * 2 + 0];
        s1 += pv * Wout[k * 2 + 1];
    }
    #pragma unroll
    for (int i = 0; i < 4; i++) g_pooled[w * HID + lane * 4 + i] = 0.0f;
    #pragma unroll
    for (int off = 16; off; off >>= 1) {
        s0 += __shfl_xor_sync(0xFFFFFFFFu, s0, off);
        s1 += __shfl_xor_sync(0xFFFFFFFFu, s1, off);
    }
    if (lane == 0) {
        out[w * 2 + 0] = s0 + bout[0];
        out[w * 2 + 1] = s1 + bout[1];
    }
}

// ---------------- launch ----------------
extern "C" void kernel_launch(void* const* d_in, const int* in_sizes, int n_in,
                              void* d_out, int out_size) {
    const float* x     = (const float*)d_in[0];
    const int*   ei    = (const int*)d_in[1];
    const int*   src   = ei;
    const int*   dst   = ei + N_EDGES;
    const int*   batch = (const int*)d_in[2];
    const float* Wl    = (const float*)d_in[3];
    const float* Wr    = (const float*)d_in[4];
    const float* bl    = (const float*)d_in[5];
    const float* Wout  = (const float*)d_in[6];
    const float* bout  = (const float*)d_in[7];
    float* out = (float*)d_out;

    __nv_bfloat16* wt;
    float* f;
    cudaGetSymbolAddress((void**)&wt, g_wt);
    cudaGetSymbolAddress((void**)&f, g_f);

    static bool attr_done = false;
    if (!attr_done) {
        cudaFuncSetAttribute(k_gemm, cudaFuncAttributeMaxDynamicSharedMemorySize, GEMM_SMEM);
        attr_done = true;
    }

    // launches 1-3: CSR build + weight/x prep (deg/cursor/pooled are 0 at entry)
    k_pre<<<(N_NODES * HID / 4 + 255) / 256, 256>>>(dst, x, Wl, Wr);
    k_scan<<<(N_NODES + 1023) / 1024, 1024>>>();
    k_fill<<<(N_EDGES + 255) / 256, 256>>>(src, dst);

    // layers: agg gathers fp32 (x for layer 0, g_f after), gemm writes g_f + split
    const int GG = (N_NODES + 127) / 128;  // 391
    for (int i = 0; i < N_LAYERS; i++) {
        k_agg<<<(N_NODES * 32 + 255) / 256, 256>>>(i == 0 ? x : f);
        k_gemm<<<GG, 512, GEMM_SMEM>>>(wt + (size_t)i * 65536,
                                       bl + (size_t)i * HID,
                                       (i < N_LAYERS - 1) ? 1 : 0,
                                       (i < N_LAYERS - 1) ? 1 : 0);
    }

    k_pool<<<(N_NODES * 32 + 255) / 256, 256>>>(batch);
    k_final<<<(N_GRAPHS * 32 + 255) / 256, 256>>>(Wout, bout, out);
}